// round 3
// baseline (speedup 1.0000x reference)
#include <cuda_runtime.h>
#include <cstdint>

#define N_NODES 50000
#define DD 128
#define RR 8
#define NMAT 9              // 8 relations + root
#define NB 391              // ceil(50000/128) row bands
#define BAND_FLOATS 16384   // 128x128 operand tile in packed-fragment layout

// ---- scratch (static device globals; no runtime allocation) ----
__device__ float g_z[(size_t)N_NODES * RR * DD];          // 204.8 MB  z[n][r][d]
__device__ float g_h[(size_t)N_NODES * DD];               // 25.6 MB hidden
__device__ float g_inv[N_NODES * RR];
__device__ int   g_cnt[N_NODES * RR];
__device__ int   g_flags[2];
__device__ float g_a[(size_t)NB * BAND_FLOATS];           // A in frag-packed tf32
__device__ float g_wt[2 * NMAT * BAND_FLOATS];            // W in frag-packed tf32

// ================= helpers =================
__device__ __forceinline__ float to_tf32(float x) {
    float r;
    asm("cvt.rna.tf32.f32 %0, %1;" : "=f"(r) : "f"(x));
    return r;
}
__device__ __forceinline__ uint32_t smem_u32(const void* p) {
    uint32_t a;
    asm("{ .reg .u64 t; cvta.to.shared.u64 t, %1; cvt.u32.u64 %0, t; }" : "=r"(a) : "l"(p));
    return a;
}
__device__ __forceinline__ void cp_async16(uint32_t saddr, const void* gptr) {
    asm volatile("cp.async.cg.shared.global [%0], [%1], 16;"
                 :: "r"(saddr), "l"(__cvta_generic_to_global(gptr)) : "memory");
}
#define CP_COMMIT() asm volatile("cp.async.commit_group;" ::: "memory")
#define CP_WAIT1()  asm volatile("cp.async.wait_group 1;" ::: "memory")

__device__ __forceinline__ void mma_tf32(float* c, const uint4 a, const uint2 b) {
    asm volatile(
        "mma.sync.aligned.m16n8k8.row.col.f32.tf32.tf32.f32 "
        "{%0,%1,%2,%3}, {%4,%5,%6,%7}, {%8,%9}, {%0,%1,%2,%3};"
        : "+f"(c[0]), "+f"(c[1]), "+f"(c[2]), "+f"(c[3])
        : "r"(a.x), "r"(a.y), "r"(a.z), "r"(a.w), "r"(b.x), "r"(b.y));
}

// ================= setup / conversion =================
__global__ void setup_kernel(const unsigned* __restrict__ ei,
                             const unsigned* __restrict__ et, int n) {
    int i = blockIdx.x * blockDim.x + threadIdx.x;
    if (i < n) g_cnt[i] = 0;
    if (blockIdx.x == 0 && threadIdx.x == 0) {
        unsigned a = 0, b = 0;
        for (int j = 1; j < 64; j += 2) { a |= ei[j]; b |= et[j]; }
        g_flags[0] = (a == 0) ? 1 : 0;
        g_flags[1] = (b == 0) ? 1 : 0;
    }
}

__device__ __forceinline__ long long ld_idx(const void* p, long long i, int is64) {
    return is64 ? ((const long long*)p)[i] : (long long)((const int*)p)[i];
}

__global__ void count_kernel(const void* __restrict__ ei,
                             const void* __restrict__ et, int E) {
    int e = blockIdx.x * blockDim.x + threadIdx.x;
    if (e >= E) return;
    int dst = (int)ld_idx(ei, (long long)E + e, g_flags[0]);
    int rel = (int)ld_idx(et, e, g_flags[1]);
    atomicAdd(&g_cnt[dst * RR + rel], 1);
}

__global__ void inv_kernel(int n) {
    int i = blockIdx.x * blockDim.x + threadIdx.x;
    if (i < n) {
        int c = g_cnt[i];
        g_inv[i] = 1.0f / (float)(c > 0 ? c : 1);
    }
}

// fp32 A (optionally relu) -> tf32 fragment-packed g_a.
// Fragment map (m16n8k8): A[r16][c8]: lane=(r&7)*4+(c&3), slot=(r>>3)+2*(c>>2)
__global__ void conv_kernel(const float* __restrict__ src, int do_relu, int nrows) {
    int i = blockIdx.x * blockDim.x + threadIdx.x;
    if (i >= NB * BAND_FLOATS) return;
    int n = i >> 7, k = i & 127;
    const float* s = src ? src : g_h;
    float v = 0.f;
    if (n < nrows) {
        v = s[(size_t)n * DD + k];
        if (do_relu) v = fmaxf(v, 0.f);
        v = to_tf32(v);
    }
    int band = n >> 7, r = n & 127;
    int mt = r >> 4, rr = r & 15;
    int kc = k >> 3;
    int lane = (rr & 7) * 4 + (k & 3);
    int slot = (rr >> 3) + 2 * ((k >> 2) & 1);
    g_a[((((size_t)band * 16 + kc) * 8 + mt) * 32 + lane) * 4 + slot] = v;
}

// W (k-major [k][n]) -> tf32 fragment-packed g_wt.
// B frag (m16n8k8 col): b_slot = (k&7)>>2, lane=(n&7)*4+(k&3)
__global__ void wconv_kernel(const float* __restrict__ w1, const float* __restrict__ r1,
                             const float* __restrict__ w2, const float* __restrict__ r2) {
    int l = blockIdx.x / NMAT, m = blockIdx.x % NMAT;
    const float* src = (l == 0) ? (m < RR ? w1 + (size_t)m * DD * DD : r1)
                                : (m < RR ? w2 + (size_t)m * DD * DD : r2);
    float* dst = g_wt + (size_t)(l * NMAT + m) * BAND_FLOATS;
    for (int idx = threadIdx.x; idx < DD * DD; idx += blockDim.x) {
        int k = idx >> 7, n = idx & 127;
        float v = to_tf32(src[idx]);
        int kc = k >> 3, nt = n >> 3;
        int lane = (n & 7) * 4 + (k & 3);
        int slot = (k >> 2) & 1;
        dst[((kc * 16 + nt) * 32 + lane) * 2 + slot] = v;
    }
}

// ================= persistent tf32 GEMM =================
// grid (9, 16): x = matrix (8 relations + root), y = band stripe.
// smem: Bs 64KB | As[2] 2x64KB  (cp.async double buffer)
#define SM_B 0
#define SM_A0 65536
#define SM_A1 131072
#define SM_TOTAL 196608

__global__ __launch_bounds__(256, 1)
void gemm_tc(int layer, const float* __restrict__ bias,
             float* __restrict__ dout, int nrows) {
    extern __shared__ char smem[];
    uint32_t sb = smem_u32(smem);
    float* Bs = (float*)smem;

    int tid = threadIdx.x;
    int lane = tid & 31, wid = tid >> 5;
    int wm = wid & 1, wn = wid >> 1;          // 2x4 warps -> 64x32 tiles
    int bz = blockIdx.x;

    // stage B once
    {
        const float4* Bg = (const float4*)(g_wt + (size_t)(layer * NMAT + bz) * BAND_FLOATS);
        float4* B4 = (float4*)Bs;
        for (int i = tid; i < 4096; i += 256) B4[i] = Bg[i];
    }

    int band = blockIdx.y;
    int stride = gridDim.y;

    // prefetch first band into As0
    if (band < NB) {
        const char* src = (const char*)(g_a + (size_t)band * BAND_FLOATS);
#pragma unroll
        for (int j = 0; j < 16; j++)
            cp_async16(sb + SM_A0 + (j * 256 + tid) * 16, src + (j * 256 + tid) * 16);
    }
    CP_COMMIT();

    int buf = 0;
    while (band < NB) {
        int next = band + stride;
        if (next < NB) {
            const char* src = (const char*)(g_a + (size_t)next * BAND_FLOATS);
            uint32_t dsts = sb + (buf ? SM_A0 : SM_A1);
#pragma unroll
            for (int j = 0; j < 16; j++)
                cp_async16(dsts + (j * 256 + tid) * 16, src + (j * 256 + tid) * 16);
        }
        CP_COMMIT();
        CP_WAIT1();
        __syncthreads();   // current band ready in As[buf]; B ready (first iter)

        const float* As = (const float*)(smem + (buf ? SM_A1 : SM_A0));

        float acc[4][4][4];
#pragma unroll
        for (int i = 0; i < 4; i++)
#pragma unroll
            for (int j = 0; j < 4; j++)
#pragma unroll
                for (int q = 0; q < 4; q++) acc[i][j][q] = 0.f;

#pragma unroll
        for (int kc = 0; kc < 16; kc++) {
            uint4 aF[4];
            uint2 bF[4];
#pragma unroll
            for (int mf = 0; mf < 4; mf++)
                aF[mf] = *(const uint4*)(As + ((kc * 8 + wm * 4 + mf) * 32 + lane) * 4);
#pragma unroll
            for (int nf = 0; nf < 4; nf++)
                bF[nf] = *(const uint2*)(Bs + ((kc * 16 + wn * 4 + nf) * 32 + lane) * 2);
#pragma unroll
            for (int mf = 0; mf < 4; mf++)
#pragma unroll
                for (int nf = 0; nf < 4; nf++)
                    mma_tf32(acc[mf][nf], aF[mf], bF[nf]);
        }

        // epilogue
        int n0 = band * 128;
#pragma unroll
        for (int mf = 0; mf < 4; mf++) {
            int r0 = wm * 64 + mf * 16 + (lane >> 2);
#pragma unroll
            for (int nf = 0; nf < 4; nf++) {
                int col = wn * 32 + nf * 8 + 2 * (lane & 3);
#pragma unroll
                for (int h = 0; h < 2; h++) {
                    int gr = n0 + r0 + h * 8;
                    if (gr < nrows) {
                        float v0 = acc[mf][nf][h * 2 + 0];
                        float v1 = acc[mf][nf][h * 2 + 1];
                        if (bz < RR) {
                            *(float2*)(g_z + ((size_t)gr * RR + bz) * DD + col) =
                                make_float2(v0, v1);
                        } else {
                            float* o = dout ? dout : g_h;
                            *(float2*)(o + (size_t)gr * DD + col) =
                                make_float2(v0 + bias[col], v1 + bias[col + 1]);
                        }
                    }
                }
            }
        }
        __syncthreads();   // all reads of As[buf] done before it is refilled
        buf ^= 1;
        band = next;
    }
}

// ================= edge aggregation =================
__global__ void edge_agg_kernel(const void* __restrict__ ei,
                                const void* __restrict__ et,
                                int E, float* __restrict__ dout) {
    int gw = (blockIdx.x * blockDim.x + threadIdx.x) >> 5;
    int lane = threadIdx.x & 31;
    if (gw >= E) return;
    float* out = dout ? dout : g_h;
    int is64i = g_flags[0], is64t = g_flags[1];
    long long src, dst;
    if (is64i) {
        const long long* p = (const long long*)ei;
        src = p[gw]; dst = p[(long long)E + gw];
    } else {
        const int* p = (const int*)ei;
        src = p[gw]; dst = p[E + gw];
    }
    int rel = (int)(is64t ? ((const long long*)et)[gw] : (long long)((const int*)et)[gw]);

    float s = g_inv[(int)dst * RR + rel];
    const float4 v = *(const float4*)(g_z + ((size_t)src * RR + rel) * DD + lane * 4);
    float* dp = out + (size_t)dst * DD + lane * 4;
    asm volatile("red.global.add.v4.f32 [%0], {%1,%2,%3,%4};"
                 :: "l"(dp), "f"(v.x * s), "f"(v.y * s), "f"(v.z * s), "f"(v.w * s)
                 : "memory");
}

__global__ void relu_kernel(float* __restrict__ p, int n4) {
    int i = blockIdx.x * blockDim.x + threadIdx.x;
    if (i >= n4) return;
    float4 v = ((float4*)p)[i];
    v.x = fmaxf(v.x, 0.f); v.y = fmaxf(v.y, 0.f);
    v.z = fmaxf(v.z, 0.f); v.w = fmaxf(v.w, 0.f);
    ((float4*)p)[i] = v;
}

// =================================================================
extern "C" void kernel_launch(void* const* d_in, const int* in_sizes, int n_in,
                              void* d_out, int out_size) {
    const float* x     = (const float*)d_in[0];
    const void*  ei    = d_in[1];
    const void*  et    = d_in[2];
    const float* w1    = (const float*)d_in[3];
    const float* root1 = (const float*)d_in[4];
    const float* b1    = (const float*)d_in[5];
    const float* w2    = (const float*)d_in[6];
    const float* root2 = (const float*)d_in[7];
    const float* b2    = (const float*)d_in[8];
    float* out = (float*)d_out;

    int E = in_sizes[2];
    int N = in_sizes[0] / DD;

    cudaFuncSetAttribute(gemm_tc, cudaFuncAttributeMaxDynamicSharedMemorySize, SM_TOTAL);

    int nr = N * RR;
    int conv_total = NB * BAND_FLOATS;
    int edge_blocks = (E * 32 + 255) / 256;
    int relu_n4 = N * DD / 4;
    dim3 gg(NMAT, 16);

    // launch order keeps gemm_tc at index 5 for ncu -s 5 -c 1
    setup_kernel<<<(nr + 255) / 256, 256>>>((const unsigned*)ei, (const unsigned*)et, nr); // 0
    count_kernel<<<(E + 255) / 256, 256>>>(ei, et, E);                                     // 1
    inv_kernel<<<(nr + 255) / 256, 256>>>(nr);                                             // 2
    conv_kernel<<<(conv_total + 255) / 256, 256>>>(x, 0, N);                               // 3
    wconv_kernel<<<2 * NMAT, 256>>>(w1, root1, w2, root2);                                 // 4

    // layer 1: x -> g_h
    gemm_tc<<<gg, 256, SM_TOTAL>>>(0, b1, nullptr, N);                                     // 5 <- ncu
    edge_agg_kernel<<<edge_blocks, 256>>>(ei, et, E, nullptr);                             // 6
    conv_kernel<<<(conv_total + 255) / 256, 256>>>(nullptr, 1, N);                         // 7

    // layer 2: g_h -> out
    gemm_tc<<<gg, 256, SM_TOTAL>>>(1, b2, out, N);                                         // 8
    edge_agg_kernel<<<edge_blocks, 256>>>(ei, et, E, out);                                 // 9
    relu_kernel<<<(relu_n4 + 255) / 256, 256>>>(out, relu_n4);                             // 10
}